// round 1
// baseline (speedup 1.0000x reference)
#include <cuda_runtime.h>
#include <cuda_bf16.h>
#include <cstdint>

#define BATCH   2
#define SEQ     2048
#define DIM     2048
#define NHEADS  32
#define NKVH    8
#define HD      64
#define QKVROW  ((NHEADS + 2*NKVH) * HD)   // 3072
#define MROWS   (BATCH * SEQ)              // 4096

// Scratch (allocation-free rule: __device__ globals)
__device__ float g_qkv[(size_t)MROWS * QKVROW];   // ~50 MB
__device__ float g_attn[(size_t)MROWS * DIM];     // ~33.5 MB

// ---------------------------------------------------------------------------
// SGEMM: C[M,N] = A[M,K] @ B[N,K]^T   (both row-major, K-contiguous)
// 128x128 tile, BK=16, 256 threads, 8x8 per thread, fp32
// ---------------------------------------------------------------------------
__global__ __launch_bounds__(256, 2)
void sgemm_nt(const float* __restrict__ A, const float* __restrict__ B,
              float* __restrict__ C, int M, int N, int K)
{
    __shared__ float As[16][128];
    __shared__ float Bs[16][128];

    const int tid = threadIdx.x;
    const int tx  = tid & 15;        // 0..15 -> 8 cols each
    const int ty  = tid >> 4;        // 0..15 -> 8 rows each
    const int row0 = blockIdx.y * 128;
    const int col0 = blockIdx.x * 128;

    const int lr = tid >> 2;         // 0..63
    const int lc = (tid & 3) << 2;   // 0,4,8,12

    const float* Ag = A + (size_t)(row0 + lr) * K + lc;
    const float* Bg = B + (size_t)(col0 + lr) * K + lc;

    float acc[8][8];
#pragma unroll
    for (int i = 0; i < 8; i++)
#pragma unroll
        for (int j = 0; j < 8; j++) acc[i][j] = 0.f;

    for (int k0 = 0; k0 < K; k0 += 16) {
#pragma unroll
        for (int rr = 0; rr < 2; rr++) {
            const int r = lr + rr * 64;
            float4 va = *(const float4*)(Ag + (size_t)rr * 64 * K + k0);
            float4 vb = *(const float4*)(Bg + (size_t)rr * 64 * K + k0);
            As[lc + 0][r] = va.x; As[lc + 1][r] = va.y;
            As[lc + 2][r] = va.z; As[lc + 3][r] = va.w;
            Bs[lc + 0][r] = vb.x; Bs[lc + 1][r] = vb.y;
            Bs[lc + 2][r] = vb.z; Bs[lc + 3][r] = vb.w;
        }
        __syncthreads();

#pragma unroll
        for (int kk = 0; kk < 16; kk++) {
            float a[8], b[8];
            *(float4*)&a[0] = *(const float4*)&As[kk][ty * 8];
            *(float4*)&a[4] = *(const float4*)&As[kk][ty * 8 + 4];
            *(float4*)&b[0] = *(const float4*)&Bs[kk][tx * 8];
            *(float4*)&b[4] = *(const float4*)&Bs[kk][tx * 8 + 4];
#pragma unroll
            for (int i = 0; i < 8; i++)
#pragma unroll
                for (int j = 0; j < 8; j++)
                    acc[i][j] += a[i] * b[j];
        }
        __syncthreads();
    }

#pragma unroll
    for (int i = 0; i < 8; i++) {
        const size_t r = (size_t)(row0 + ty * 8 + i);
#pragma unroll
        for (int j = 0; j < 8; j += 4) {
            float4 v = make_float4(acc[i][j], acc[i][j + 1], acc[i][j + 2], acc[i][j + 3]);
            *(float4*)(C + r * N + col0 + tx * 8 + j) = v;
        }
    }
}

// ---------------------------------------------------------------------------
// Flash attention (fp32, causal, GQA). One block = 64 query rows of one head.
// smem: Qs [d][r], Ks [d][c], Vs [k][d], Ps [k][r], stride FPAD=68.
// 256 threads, 4x4 micro-tile. Online softmax (m, l per row).
// ---------------------------------------------------------------------------
#define FPAD 68
#define FLASH_SMEM (4 * 64 * FPAD * sizeof(float))   // 69632 B

__global__ __launch_bounds__(256)
void flash_attn(const float* __restrict__ qkv, float* __restrict__ attn_out)
{
    extern __shared__ float sm[];
    float* Qs = sm;                 // [64][FPAD]  (d-major, r inner)
    float* Ks = Qs + 64 * FPAD;     // [64][FPAD]  (d-major, c inner)
    float* Vs = Ks + 64 * FPAD;     // [64][FPAD]  (k-major, d inner)
    float* Ps = Vs + 64 * FPAD;     // [64][FPAD]  (k-major, r inner)

    const int tid = threadIdx.x;
    const int tx  = tid & 15;       // col group (4 cols)
    const int ty  = tid >> 4;       // row group (4 rows)
    const int b   = blockIdx.z;
    const int h   = blockIdx.y;
    // launch heaviest q-tiles first for better tail balance
    const int qi  = gridDim.x - 1 - blockIdx.x;
    const int kvh = h & (NKVH - 1);
    const int q0  = qi * 64;
    const float scale = 0.125f;     // 1/sqrt(64)

    // load Q tile transposed: Qs[d][r]
    for (int t = tid; t < 64 * 16; t += 256) {
        const int r  = t >> 4;
        const int dv = (t & 15) << 2;
        float4 v = *(const float4*)(qkv + ((size_t)(b * SEQ + q0 + r) * 48 + h) * 64 + dv);
        Qs[(dv + 0) * FPAD + r] = v.x;
        Qs[(dv + 1) * FPAD + r] = v.y;
        Qs[(dv + 2) * FPAD + r] = v.z;
        Qs[(dv + 3) * FPAD + r] = v.w;
    }

    float m_i[4], l_i[4], o[4][4];
#pragma unroll
    for (int i = 0; i < 4; i++) {
        m_i[i] = -1e30f; l_i[i] = 0.f;
#pragma unroll
        for (int j = 0; j < 4; j++) o[i][j] = 0.f;
    }

    for (int kt = 0; kt <= qi; kt++) {
        const int k0 = kt * 64;
        // load K (transposed) and V (natural)
        for (int t = tid; t < 64 * 16; t += 256) {
            const int r  = t >> 4;
            const int dv = (t & 15) << 2;
            const size_t base = (size_t)(b * SEQ + k0 + r) * QKVROW;
            float4 kk4 = *(const float4*)(qkv + base + (size_t)(NHEADS + kvh) * 64 + dv);
            Ks[(dv + 0) * FPAD + r] = kk4.x;
            Ks[(dv + 1) * FPAD + r] = kk4.y;
            Ks[(dv + 2) * FPAD + r] = kk4.z;
            Ks[(dv + 3) * FPAD + r] = kk4.w;
            float4 vv4 = *(const float4*)(qkv + base + (size_t)(NHEADS + NKVH + kvh) * 64 + dv);
            *(float4*)&Vs[r * FPAD + dv] = vv4;
        }
        __syncthreads();

        // S = Q @ K^T  (64x64x64)
        float s[4][4];
#pragma unroll
        for (int i = 0; i < 4; i++)
#pragma unroll
            for (int j = 0; j < 4; j++) s[i][j] = 0.f;

#pragma unroll 8
        for (int d = 0; d < 64; d++) {
            float4 a  = *(const float4*)&Qs[d * FPAD + ty * 4];
            float4 bb = *(const float4*)&Ks[d * FPAD + tx * 4];
            const float av[4] = {a.x, a.y, a.z, a.w};
            const float bv[4] = {bb.x, bb.y, bb.z, bb.w};
#pragma unroll
            for (int i = 0; i < 4; i++)
#pragma unroll
                for (int j = 0; j < 4; j++)
                    s[i][j] += av[i] * bv[j];
        }

        const bool diag = (kt == qi);
        float p[4][4];
#pragma unroll
        for (int i = 0; i < 4; i++) {
            const int row = q0 + ty * 4 + i;
            float rmax = -1e30f;
#pragma unroll
            for (int j = 0; j < 4; j++) {
                float v = s[i][j] * scale;
                if (diag && (k0 + tx * 4 + j) > row) v = -1e30f;
                s[i][j] = v;
                rmax = fmaxf(rmax, v);
            }
            // reduce max over 16 lanes owning this row (half-warp)
#pragma unroll
            for (int off = 8; off >= 1; off >>= 1)
                rmax = fmaxf(rmax, __shfl_xor_sync(0xffffffffu, rmax, off));

            const float mnew  = fmaxf(m_i[i], rmax);
            const float alpha = __expf(m_i[i] - mnew);
            float rs = 0.f;
#pragma unroll
            for (int j = 0; j < 4; j++) {
                p[i][j] = __expf(s[i][j] - mnew);
                rs += p[i][j];
            }
#pragma unroll
            for (int off = 8; off >= 1; off >>= 1)
                rs += __shfl_xor_sync(0xffffffffu, rs, off);

            l_i[i] = l_i[i] * alpha + rs;
            m_i[i] = mnew;
#pragma unroll
            for (int j = 0; j < 4; j++) o[i][j] *= alpha;
        }

        // P -> smem, transposed: Ps[k][r]
#pragma unroll
        for (int j = 0; j < 4; j++)
#pragma unroll
            for (int i = 0; i < 4; i++)
                Ps[(tx * 4 + j) * FPAD + ty * 4 + i] = p[i][j];
        __syncthreads();

        // O += P @ V  (64x64x64)
#pragma unroll 8
        for (int k = 0; k < 64; k++) {
            float4 a  = *(const float4*)&Ps[k * FPAD + ty * 4];
            float4 bb = *(const float4*)&Vs[k * FPAD + tx * 4];
            const float av[4] = {a.x, a.y, a.z, a.w};
            const float bv[4] = {bb.x, bb.y, bb.z, bb.w};
#pragma unroll
            for (int i = 0; i < 4; i++)
#pragma unroll
                for (int j = 0; j < 4; j++)
                    o[i][j] += av[i] * bv[j];
        }
        __syncthreads();   // protect Ks/Vs/Ps before next iteration's loads
    }

    // epilogue: normalize, write attn_out[b*SEQ + q, h*64 + d]
#pragma unroll
    for (int i = 0; i < 4; i++) {
        const float inv = 1.f / l_i[i];
        float4 v = make_float4(o[i][0] * inv, o[i][1] * inv, o[i][2] * inv, o[i][3] * inv);
        *(float4*)(attn_out + (size_t)(b * SEQ + q0 + ty * 4 + i) * DIM + h * 64 + tx * 4) = v;
    }
}

// ---------------------------------------------------------------------------
extern "C" void kernel_launch(void* const* d_in, const int* in_sizes, int n_in,
                              void* d_out, int out_size)
{
    const float* x    = (const float*)d_in[0];   // [2,2048,2048]
    const float* Wqkv = (const float*)d_in[1];   // [3072,2048]
    const float* Wout = (const float*)d_in[2];   // [2048,2048]
    float* out = (float*)d_out;                  // [2,2048,2048]

    float* qkv;  cudaGetSymbolAddress((void**)&qkv,  g_qkv);
    float* attn; cudaGetSymbolAddress((void**)&attn, g_attn);

    cudaFuncSetAttribute(flash_attn, cudaFuncAttributeMaxDynamicSharedMemorySize,
                         (int)FLASH_SMEM);

    // 1) qkv = x @ Wqkv^T : [4096,3072]
    {
        dim3 grid(QKVROW / 128, MROWS / 128);
        sgemm_nt<<<grid, 256>>>(x, Wqkv, qkv, MROWS, QKVROW, DIM);
    }
    // 2) causal GQA flash attention
    {
        dim3 grid(SEQ / 64, NHEADS, BATCH);
        flash_attn<<<grid, 256, FLASH_SMEM>>>(qkv, attn);
    }
    // 3) out = attn @ Wout^T : [4096,2048]
    {
        dim3 grid(DIM / 128, MROWS / 128);
        sgemm_nt<<<grid, 256>>>(attn, Wout, out, MROWS, DIM, DIM);
    }
}

// round 3
// speedup vs baseline: 7.1343x; 7.1343x over previous
#include <cuda_runtime.h>
#include <cuda_fp16.h>
#include <cstdint>

#define BATCH   2
#define SEQ     2048
#define DIM     2048
#define NHEADS  32
#define NKVH    8
#define HD      64
#define QKVROW  3072
#define MROWS   4096

// ---------------- scratch (__device__ globals; no allocs) ------------------
__device__ __half g_xh  [(size_t)MROWS  * DIM];
__device__ __half g_wqh [(size_t)QKVROW * DIM];
__device__ __half g_woh [(size_t)DIM    * DIM];
__device__ __half g_qkvh[(size_t)MROWS  * QKVROW];
__device__ __half g_atth[(size_t)MROWS  * DIM];

// ---------------- helpers ---------------------------------------------------
__device__ __forceinline__ uint32_t smem_u32(const void* p) {
    uint32_t a;
    asm("{ .reg .u64 t; cvta.to.shared.u64 t, %1; cvt.u32.u64 %0, t; }" : "=r"(a) : "l"(p));
    return a;
}
#define SWZ128(off) ((off) ^ (((off) >> 3) & 0x70))

__device__ __forceinline__ void cp16(uint32_t dst, const void* src) {
    asm volatile("cp.async.cg.shared.global [%0], [%1], 16;" :: "r"(dst), "l"(src) : "memory");
}
__device__ __forceinline__ void cp_commit() {
    asm volatile("cp.async.commit_group;" ::: "memory");
}
template <int N>
__device__ __forceinline__ void cp_wait() {
    asm volatile("cp.async.wait_group %0;" :: "n"(N) : "memory");
}
__device__ __forceinline__ void ldsm4(uint32_t* r, uint32_t addr) {
    asm volatile("ldmatrix.sync.aligned.m8n8.x4.shared.b16 {%0,%1,%2,%3}, [%4];"
                 : "=r"(r[0]), "=r"(r[1]), "=r"(r[2]), "=r"(r[3]) : "r"(addr));
}
__device__ __forceinline__ void ldsm4t(uint32_t* r, uint32_t addr) {
    asm volatile("ldmatrix.sync.aligned.m8n8.x4.trans.shared.b16 {%0,%1,%2,%3}, [%4];"
                 : "=r"(r[0]), "=r"(r[1]), "=r"(r[2]), "=r"(r[3]) : "r"(addr));
}
__device__ __forceinline__ void mma16816(float* c, const uint32_t* a, const uint32_t* b) {
    asm volatile("mma.sync.aligned.m16n8k16.row.col.f32.f16.f16.f32 "
                 "{%0,%1,%2,%3}, {%4,%5,%6,%7}, {%8,%9}, {%0,%1,%2,%3};"
                 : "+f"(c[0]), "+f"(c[1]), "+f"(c[2]), "+f"(c[3])
                 : "r"(a[0]), "r"(a[1]), "r"(a[2]), "r"(a[3]), "r"(b[0]), "r"(b[1]));
}

// ---------------------------------------------------------------------------
// fp32 -> fp16 conversion (memory-bound)
// ---------------------------------------------------------------------------
__global__ void to_half(const float* __restrict__ in, __half* __restrict__ out, int n)
{
    int i = (blockIdx.x * blockDim.x + threadIdx.x) * 8;
    if (i >= n) return;
    float4 a = *(const float4*)(in + i);
    float4 b = *(const float4*)(in + i + 4);
    __half2* o = (__half2*)(out + i);
    o[0] = __floats2half2_rn(a.x, a.y);
    o[1] = __floats2half2_rn(a.z, a.w);
    o[2] = __floats2half2_rn(b.x, b.y);
    o[3] = __floats2half2_rn(b.z, b.w);
}

// ---------------------------------------------------------------------------
// HMMA GEMM: C[M,N] = A[M,K] @ B[N,K]^T   (fp16 in, fp32 accum)
// BM=BN=128, BK=64, 8 warps (warp tile 32x64), 3-stage cp.async, SW128 smem.
// ---------------------------------------------------------------------------
#define GBK   64
#define ASZ   (128 * 128)            // 16384 B per A stage
#define GSTG_B (2 * ASZ)             // 32768 B per stage (A + B)
#define GEMM_SMEM (3 * GSTG_B)       // 98304 B

template<bool HALF_OUT>
__global__ __launch_bounds__(256)
void gemm_h(const __half* __restrict__ A, const __half* __restrict__ B,
            void* __restrict__ Cv, int M, int N, int K)
{
    extern __shared__ char smem[];
    const uint32_t sb0 = smem_u32(smem);
    const int tid = threadIdx.x, lane = tid & 31, wid = tid >> 5;
    const int wm = wid & 3, wn = wid >> 2;
    const int row0 = blockIdx.y * 128, col0 = blockIdx.x * 128;
    const int NITER = K / GBK;

    auto load_stage = [&](int s, int c) {
        const int k0 = c * GBK;
        const uint32_t sA = sb0 + s * GSTG_B, sB = sA + ASZ;
#pragma unroll
        for (int t = 0; t < 4; t++) {
            int idx = tid + t * 256;           // 0..1023 : 128 rows x 8 chunks
            int r = idx >> 3, cc = idx & 7;
            uint32_t off = SWZ128((uint32_t)(r * 128 + cc * 16));
            cp16(sA + off, A + (size_t)(row0 + r) * K + k0 + cc * 8);
            cp16(sB + off, B + (size_t)(col0 + r) * K + k0 + cc * 8);
        }
        cp_commit();
    };

    float acc[2][8][4];
#pragma unroll
    for (int a = 0; a < 2; a++)
#pragma unroll
        for (int b = 0; b < 8; b++)
#pragma unroll
            for (int c = 0; c < 4; c++) acc[a][b][c] = 0.f;

    load_stage(0, 0);
    load_stage(1, 1);

    for (int i = 0; i < NITER; i++) {
        if (i + 2 < NITER) { load_stage((i + 2) % 3, i + 2); cp_wait<2>(); }
        else if (i + 1 < NITER) cp_wait<1>();
        else cp_wait<0>();
        __syncthreads();

        const uint32_t sA = sb0 + (i % 3) * GSTG_B, sB = sA + ASZ;
#pragma unroll
        for (int ks = 0; ks < 4; ks++) {
            uint32_t af[2][4];
#pragma unroll
            for (int mt = 0; mt < 2; mt++)
                ldsm4(af[mt], sA + SWZ128((uint32_t)((wm * 32 + mt * 16 + (lane & 15)) * 128
                                                      + (ks * 2 + (lane >> 4)) * 16)));
#pragma unroll
            for (int bt = 0; bt < 4; bt++) {
                uint32_t bf[4];
                ldsm4(bf, sB + SWZ128((uint32_t)((wn * 64 + bt * 16 + ((lane >> 4) << 3) + (lane & 7)) * 128
                                                  + (ks * 2 + ((lane >> 3) & 1)) * 16)));
#pragma unroll
                for (int mt = 0; mt < 2; mt++) {
                    mma16816(acc[mt][2 * bt],     af[mt], bf);
                    mma16816(acc[mt][2 * bt + 1], af[mt], bf + 2);
                }
            }
        }
        __syncthreads();
    }

#pragma unroll
    for (int mt = 0; mt < 2; mt++) {
#pragma unroll
        for (int nt = 0; nt < 8; nt++) {
            const int col = col0 + wn * 64 + nt * 8 + (lane & 3) * 2;
            const int r0  = row0 + wm * 32 + mt * 16 + (lane >> 2);
            if (HALF_OUT) {
                __half* C = (__half*)Cv;
                *(__half2*)(C + (size_t)r0 * N + col)       = __floats2half2_rn(acc[mt][nt][0], acc[mt][nt][1]);
                *(__half2*)(C + (size_t)(r0 + 8) * N + col) = __floats2half2_rn(acc[mt][nt][2], acc[mt][nt][3]);
            } else {
                float* C = (float*)Cv;
                *(float2*)(C + (size_t)r0 * N + col)       = make_float2(acc[mt][nt][0], acc[mt][nt][1]);
                *(float2*)(C + (size_t)(r0 + 8) * N + col) = make_float2(acc[mt][nt][2], acc[mt][nt][3]);
            }
        }
    }
}

// ---------------------------------------------------------------------------
// Flash attention, fp16 HMMA. Block = 64 q rows of one head, 128 threads.
// smem: Q[64x128B] + 2 stages of (K[8K] + V[8K]) = 40960 B.
// ---------------------------------------------------------------------------
#define FKV       8192
#define FSTG      16384
#define FLASH_SMEM (8192 + 2 * FSTG)

__global__ __launch_bounds__(128)
void flash_h(const __half* __restrict__ qkv, __half* __restrict__ attnh)
{
    extern __shared__ char smem[];
    const uint32_t sb = smem_u32(smem);
    const int tid = threadIdx.x, lane = tid & 31, wq = tid >> 5;
    const int b = blockIdx.z, h = blockIdx.y;
    const int qi  = gridDim.x - 1 - blockIdx.x;     // heavy tiles first
    const int kvh = h & (NKVH - 1);
    const int q0  = qi * 64;

    // Q tile -> smem (plain 16B loads, swizzled)
    for (int t = tid; t < 512; t += 128) {
        int r = t >> 3, cc = t & 7;
        uint4 v = *(const uint4*)(qkv + (size_t)(b * SEQ + q0 + r) * QKVROW + h * HD + cc * 8);
        *(uint4*)(smem + SWZ128((uint32_t)(r * 128 + cc * 16))) = v;
    }

    auto load_kv = [&](int s, int kt) {
        const int k0 = kt * 64;
        const uint32_t sK = sb + FKV + s * FSTG, sV = sK + 8192;
        for (int t = tid; t < 512; t += 128) {
            int r = t >> 3, cc = t & 7;
            uint32_t off = SWZ128((uint32_t)(r * 128 + cc * 16));
            const __half* base = qkv + (size_t)(b * SEQ + k0 + r) * QKVROW;
            cp16(sK + off, base + (NHEADS + kvh) * HD + cc * 8);
            cp16(sV + off, base + (NHEADS + NKVH + kvh) * HD + cc * 8);
        }
        cp_commit();
    };

    float m0 = -1e30f, m1 = -1e30f, l0 = 0.f, l1 = 0.f;
    float oacc[8][4];
#pragma unroll
    for (int j = 0; j < 8; j++)
#pragma unroll
        for (int c = 0; c < 4; c++) oacc[j][c] = 0.f;

    load_kv(0, 0);

    for (int kt = 0; kt <= qi; kt++) {
        if (kt < qi) { load_kv((kt + 1) & 1, kt + 1); cp_wait<1>(); }
        else cp_wait<0>();
        __syncthreads();
        const uint32_t sK = sb + FKV + (kt & 1) * FSTG, sV = sK + 8192;

        // S = Q @ K^T (64x64x64)
        float sacc[8][4];
#pragma unroll
        for (int j = 0; j < 8; j++)
#pragma unroll
            for (int c = 0; c < 4; c++) sacc[j][c] = 0.f;

#pragma unroll
        for (int ks = 0; ks < 4; ks++) {
            uint32_t aq[4];
            ldsm4(aq, sb + SWZ128((uint32_t)((wq * 16 + (lane & 15)) * 128
                                              + (ks * 2 + (lane >> 4)) * 16)));
#pragma unroll
            for (int bt = 0; bt < 4; bt++) {
                uint32_t bf[4];
                ldsm4(bf, sK + SWZ128((uint32_t)((bt * 16 + ((lane >> 4) << 3) + (lane & 7)) * 128
                                                  + (ks * 2 + ((lane >> 3) & 1)) * 16)));
                mma16816(sacc[2 * bt],     aq, bf);
                mma16816(sacc[2 * bt + 1], aq, bf + 2);
            }
        }

        // scale + causal mask + online softmax
        const int r0 = q0 + wq * 16 + (lane >> 2), r1 = r0 + 8;
        const int cbase = kt * 64 + (lane & 3) * 2;
        const bool diag = (kt == qi);
        float mx0 = -1e30f, mx1 = -1e30f;
#pragma unroll
        for (int j = 0; j < 8; j++) {
#pragma unroll
            for (int c = 0; c < 2; c++) {
                const int col = cbase + j * 8 + c;
                float v0 = sacc[j][c]     * 0.125f;
                float v1 = sacc[j][2 + c] * 0.125f;
                if (diag && col > r0) v0 = -1e30f;
                if (diag && col > r1) v1 = -1e30f;
                sacc[j][c] = v0; sacc[j][2 + c] = v1;
                mx0 = fmaxf(mx0, v0); mx1 = fmaxf(mx1, v1);
            }
        }
        mx0 = fmaxf(mx0, __shfl_xor_sync(0xffffffffu, mx0, 1));
        mx0 = fmaxf(mx0, __shfl_xor_sync(0xffffffffu, mx0, 2));
        mx1 = fmaxf(mx1, __shfl_xor_sync(0xffffffffu, mx1, 1));
        mx1 = fmaxf(mx1, __shfl_xor_sync(0xffffffffu, mx1, 2));

        const float mn0 = fmaxf(m0, mx0), mn1 = fmaxf(m1, mx1);
        const float al0 = __expf(m0 - mn0), al1 = __expf(m1 - mn1);

        uint32_t pf[8][2];
        float rs0 = 0.f, rs1 = 0.f;
#pragma unroll
        for (int j = 0; j < 8; j++) {
            float p0 = __expf(sacc[j][0] - mn0), p1 = __expf(sacc[j][1] - mn0);
            float p2 = __expf(sacc[j][2] - mn1), p3 = __expf(sacc[j][3] - mn1);
            rs0 += p0 + p1; rs1 += p2 + p3;
            __half2 h01 = __floats2half2_rn(p0, p1);
            __half2 h23 = __floats2half2_rn(p2, p3);
            pf[j][0] = *(uint32_t*)&h01;
            pf[j][1] = *(uint32_t*)&h23;
        }
        rs0 += __shfl_xor_sync(0xffffffffu, rs0, 1);
        rs0 += __shfl_xor_sync(0xffffffffu, rs0, 2);
        rs1 += __shfl_xor_sync(0xffffffffu, rs1, 1);
        rs1 += __shfl_xor_sync(0xffffffffu, rs1, 2);

        l0 = l0 * al0 + rs0;  l1 = l1 * al1 + rs1;
        m0 = mn0;             m1 = mn1;
#pragma unroll
        for (int j = 0; j < 8; j++) {
            oacc[j][0] *= al0; oacc[j][1] *= al0;
            oacc[j][2] *= al1; oacc[j][3] *= al1;
        }

        // O += P @ V  (V via ldmatrix.trans)
#pragma unroll
        for (int ks = 0; ks < 4; ks++) {
            uint32_t ap[4] = { pf[2 * ks][0], pf[2 * ks][1], pf[2 * ks + 1][0], pf[2 * ks + 1][1] };
#pragma unroll
            for (int vt = 0; vt < 4; vt++) {
                uint32_t vf[4];
                ldsm4t(vf, sV + SWZ128((uint32_t)((ks * 16 + ((lane >> 3) & 1) * 8 + (lane & 7)) * 128
                                                   + (2 * vt + (lane >> 4)) * 16)));
                mma16816(oacc[2 * vt],     ap, vf);
                mma16816(oacc[2 * vt + 1], ap, vf + 2);
            }
        }
        __syncthreads();
    }

    // epilogue
    const int r0 = q0 + wq * 16 + (lane >> 2), r1 = r0 + 8;
    const float il0 = 1.f / l0, il1 = 1.f / l1;
#pragma unroll
    for (int j = 0; j < 8; j++) {
        const int col = h * 64 + j * 8 + (lane & 3) * 2;
        __half2 v0 = __floats2half2_rn(oacc[j][0] * il0, oacc[j][1] * il0);
        __half2 v1 = __floats2half2_rn(oacc[j][2] * il1, oacc[j][3] * il1);
        *(__half2*)(attnh + (size_t)(b * SEQ + r0) * DIM + col) = v0;
        *(__half2*)(attnh + (size_t)(b * SEQ + r1) * DIM + col) = v1;
    }
}

// ---------------------------------------------------------------------------
extern "C" void kernel_launch(void* const* d_in, const int* in_sizes, int n_in,
                              void* d_out, int out_size)
{
    const float* x    = (const float*)d_in[0];
    const float* Wqkv = (const float*)d_in[1];
    const float* Wout = (const float*)d_in[2];
    float* out = (float*)d_out;

    __half *xh, *wqh, *woh, *qkvh, *atth;
    cudaGetSymbolAddress((void**)&xh,   g_xh);
    cudaGetSymbolAddress((void**)&wqh,  g_wqh);
    cudaGetSymbolAddress((void**)&woh,  g_woh);
    cudaGetSymbolAddress((void**)&qkvh, g_qkvh);
    cudaGetSymbolAddress((void**)&atth, g_atth);

    cudaFuncSetAttribute(gemm_h<true>,  cudaFuncAttributeMaxDynamicSharedMemorySize, GEMM_SMEM);
    cudaFuncSetAttribute(gemm_h<false>, cudaFuncAttributeMaxDynamicSharedMemorySize, GEMM_SMEM);

    // 0) fp32 -> fp16
    to_half<<<(MROWS * DIM)    / 2048, 256>>>(x,    xh,  MROWS * DIM);
    to_half<<<(QKVROW * DIM)   / 2048, 256>>>(Wqkv, wqh, QKVROW * DIM);
    to_half<<<(DIM * DIM)      / 2048, 256>>>(Wout, woh, DIM * DIM);

    // 1) qkv = x @ Wqkv^T  (fp16 out)
    {
        dim3 grid(QKVROW / 128, MROWS / 128);
        gemm_h<true><<<grid, 256, GEMM_SMEM>>>(xh, wqh, qkvh, MROWS, QKVROW, DIM);
    }
    // 2) causal GQA flash attention (fp16 HMMA, fp32 softmax)
    {
        dim3 grid(SEQ / 64, NHEADS, BATCH);
        flash_h<<<grid, 128, FLASH_SMEM>>>(qkvh, atth);
    }
    // 3) out = attn @ Wout^T  (fp32 out)
    {
        dim3 grid(DIM / 128, MROWS / 128);
        gemm_h<false><<<grid, 256, GEMM_SMEM>>>(atth, woh, out, MROWS, DIM, DIM);
    }
}

// round 4
// speedup vs baseline: 8.0337x; 1.1261x over previous
#include <cuda_runtime.h>
#include <cuda_fp16.h>
#include <cstdint>

#define BATCH   2
#define SEQ     2048
#define DIM     2048
#define NHEADS  32
#define NKVH    8
#define HD      64
#define QKVROW  3072
#define MROWS   4096

// ---------------- scratch (__device__ globals; no allocs) ------------------
__device__ __half g_xh  [(size_t)MROWS  * DIM];
__device__ __half g_wqh [(size_t)QKVROW * DIM];
__device__ __half g_woh [(size_t)DIM    * DIM];
__device__ __half g_qkvh[(size_t)MROWS  * QKVROW];
__device__ __half g_atth[(size_t)MROWS  * DIM];

// ---------------- helpers ---------------------------------------------------
__device__ __forceinline__ uint32_t smem_u32(const void* p) {
    uint32_t a;
    asm("{ .reg .u64 t; cvta.to.shared.u64 t, %1; cvt.u32.u64 %0, t; }" : "=r"(a) : "l"(p));
    return a;
}
#define SWZ128(off) ((off) ^ (((off) >> 3) & 0x70))

__device__ __forceinline__ void cp16(uint32_t dst, const void* src) {
    asm volatile("cp.async.cg.shared.global [%0], [%1], 16;" :: "r"(dst), "l"(src) : "memory");
}
__device__ __forceinline__ void cp_commit() {
    asm volatile("cp.async.commit_group;" ::: "memory");
}
template <int N>
__device__ __forceinline__ void cp_wait() {
    asm volatile("cp.async.wait_group %0;" :: "n"(N) : "memory");
}
__device__ __forceinline__ void ldsm4(uint32_t* r, uint32_t addr) {
    asm volatile("ldmatrix.sync.aligned.m8n8.x4.shared.b16 {%0,%1,%2,%3}, [%4];"
                 : "=r"(r[0]), "=r"(r[1]), "=r"(r[2]), "=r"(r[3]) : "r"(addr));
}
__device__ __forceinline__ void ldsm4t(uint32_t* r, uint32_t addr) {
    asm volatile("ldmatrix.sync.aligned.m8n8.x4.trans.shared.b16 {%0,%1,%2,%3}, [%4];"
                 : "=r"(r[0]), "=r"(r[1]), "=r"(r[2]), "=r"(r[3]) : "r"(addr));
}
__device__ __forceinline__ void mma16816(float* c, const uint32_t* a, const uint32_t* b) {
    asm volatile("mma.sync.aligned.m16n8k16.row.col.f32.f16.f16.f32 "
                 "{%0,%1,%2,%3}, {%4,%5,%6,%7}, {%8,%9}, {%0,%1,%2,%3};"
                 : "+f"(c[0]), "+f"(c[1]), "+f"(c[2]), "+f"(c[3])
                 : "r"(a[0]), "r"(a[1]), "r"(a[2]), "r"(a[3]), "r"(b[0]), "r"(b[1]));
}

// ---------------------------------------------------------------------------
// fp32 -> fp16 conversion (memory-bound)
// ---------------------------------------------------------------------------
__global__ void to_half(const float* __restrict__ in, __half* __restrict__ out, int n)
{
    int i = (blockIdx.x * blockDim.x + threadIdx.x) * 8;
    if (i >= n) return;
    float4 a = *(const float4*)(in + i);
    float4 b = *(const float4*)(in + i + 4);
    __half2* o = (__half2*)(out + i);
    o[0] = __floats2half2_rn(a.x, a.y);
    o[1] = __floats2half2_rn(a.z, a.w);
    o[2] = __floats2half2_rn(b.x, b.y);
    o[3] = __floats2half2_rn(b.z, b.w);
}

// ---------------------------------------------------------------------------
// HMMA GEMM: C[M,N] = A[M,K] @ B[N,K]^T   (fp16 in, fp32 accum)
// BM=BN=128, BK=64, 8 warps (warp tile 32x64), 3 stages, ONE sync per iter,
// loads issued AFTER the barrier (safe: buffer (i+2)%3 last read at i-1).
// __launch_bounds__(256,2): 128 regs -> 2 blocks/SM (192KB smem, 64K regs).
// ---------------------------------------------------------------------------
#define GBK   64
#define ASZ   (128 * 128)            // 16384 B per A stage
#define GSTG_B (2 * ASZ)             // 32768 B per stage (A + B)
#define GEMM_SMEM (3 * GSTG_B)       // 98304 B

template<bool HALF_OUT>
__global__ __launch_bounds__(256, 2)
void gemm_h(const __half* __restrict__ A, const __half* __restrict__ B,
            void* __restrict__ Cv, int M, int N, int K)
{
    extern __shared__ char smem[];
    const uint32_t sb0 = smem_u32(smem);
    const int tid = threadIdx.x, lane = tid & 31, wid = tid >> 5;
    const int wm = wid & 3, wn = wid >> 2;
    const int row0 = blockIdx.y * 128, col0 = blockIdx.x * 128;
    const int NITER = K / GBK;

    auto load_stage = [&](int s, int c) {
        const int k0 = c * GBK;
        const uint32_t sA = sb0 + s * GSTG_B, sB = sA + ASZ;
#pragma unroll
        for (int t = 0; t < 4; t++) {
            int idx = tid + t * 256;           // 0..1023 : 128 rows x 8 chunks
            int r = idx >> 3, cc = idx & 7;
            uint32_t off = SWZ128((uint32_t)(r * 128 + cc * 16));
            cp16(sA + off, A + (size_t)(row0 + r) * K + k0 + cc * 8);
            cp16(sB + off, B + (size_t)(col0 + r) * K + k0 + cc * 8);
        }
        cp_commit();
    };

    float acc[2][8][4];
#pragma unroll
    for (int a = 0; a < 2; a++)
#pragma unroll
        for (int b = 0; b < 8; b++)
#pragma unroll
            for (int c = 0; c < 4; c++) acc[a][b][c] = 0.f;

    load_stage(0, 0);
    load_stage(1, 1);

    for (int i = 0; i < NITER; i++) {
        if (i + 1 < NITER) cp_wait<1>(); else cp_wait<0>();
        __syncthreads();
        if (i + 2 < NITER) load_stage((i + 2) % 3, i + 2);

        const uint32_t sA = sb0 + (i % 3) * GSTG_B, sB = sA + ASZ;
#pragma unroll
        for (int ks = 0; ks < 4; ks++) {
            uint32_t af[2][4];
#pragma unroll
            for (int mt = 0; mt < 2; mt++)
                ldsm4(af[mt], sA + SWZ128((uint32_t)((wm * 32 + mt * 16 + (lane & 15)) * 128
                                                      + (ks * 2 + (lane >> 4)) * 16)));
#pragma unroll
            for (int bt = 0; bt < 4; bt++) {
                uint32_t bf[4];
                ldsm4(bf, sB + SWZ128((uint32_t)((wn * 64 + bt * 16 + ((lane >> 4) << 3) + (lane & 7)) * 128
                                                  + (ks * 2 + ((lane >> 3) & 1)) * 16)));
#pragma unroll
                for (int mt = 0; mt < 2; mt++) {
                    mma16816(acc[mt][2 * bt],     af[mt], bf);
                    mma16816(acc[mt][2 * bt + 1], af[mt], bf + 2);
                }
            }
        }
    }

#pragma unroll
    for (int mt = 0; mt < 2; mt++) {
#pragma unroll
        for (int nt = 0; nt < 8; nt++) {
            const int col = col0 + wn * 64 + nt * 8 + (lane & 3) * 2;
            const int r0  = row0 + wm * 32 + mt * 16 + (lane >> 2);
            if (HALF_OUT) {
                __half* C = (__half*)Cv;
                *(__half2*)(C + (size_t)r0 * N + col)       = __floats2half2_rn(acc[mt][nt][0], acc[mt][nt][1]);
                *(__half2*)(C + (size_t)(r0 + 8) * N + col) = __floats2half2_rn(acc[mt][nt][2], acc[mt][nt][3]);
            } else {
                float* C = (float*)Cv;
                *(float2*)(C + (size_t)r0 * N + col)       = make_float2(acc[mt][nt][0], acc[mt][nt][1]);
                *(float2*)(C + (size_t)(r0 + 8) * N + col) = make_float2(acc[mt][nt][2], acc[mt][nt][3]);
            }
        }
    }
}

// ---------------------------------------------------------------------------
// Flash attention, fp16 HMMA. Block = 64 q rows of one head, 128 threads.
// One sync per kv-tile; K/V loads issued after the barrier.
// smem: Q[8K] + 2 stages of (K[8K] + V[8K]) = 40960 B.
// ---------------------------------------------------------------------------
#define FKV       8192
#define FSTG      16384
#define FLASH_SMEM (8192 + 2 * FSTG)

__global__ __launch_bounds__(128)
void flash_h(const __half* __restrict__ qkv, __half* __restrict__ attnh)
{
    extern __shared__ char smem[];
    const uint32_t sb = smem_u32(smem);
    const int tid = threadIdx.x, lane = tid & 31, wq = tid >> 5;
    const int b = blockIdx.z, h = blockIdx.y;
    const int qi  = gridDim.x - 1 - blockIdx.x;     // heavy tiles first
    const int kvh = h & (NKVH - 1);
    const int q0  = qi * 64;

    // Q tile -> smem (plain 16B loads, swizzled)
    for (int t = tid; t < 512; t += 128) {
        int r = t >> 3, cc = t & 7;
        uint4 v = *(const uint4*)(qkv + (size_t)(b * SEQ + q0 + r) * QKVROW + h * HD + cc * 8);
        *(uint4*)(smem + SWZ128((uint32_t)(r * 128 + cc * 16))) = v;
    }

    auto load_kv = [&](int s, int kt) {
        const int k0 = kt * 64;
        const uint32_t sK = sb + FKV + s * FSTG, sV = sK + 8192;
        for (int t = tid; t < 512; t += 128) {
            int r = t >> 3, cc = t & 7;
            uint32_t off = SWZ128((uint32_t)(r * 128 + cc * 16));
            const __half* base = qkv + (size_t)(b * SEQ + k0 + r) * QKVROW;
            cp16(sK + off, base + (NHEADS + kvh) * HD + cc * 8);
            cp16(sV + off, base + (NHEADS + NKVH + kvh) * HD + cc * 8);
        }
        cp_commit();
    };

    float m0 = -1e30f, m1 = -1e30f, l0 = 0.f, l1 = 0.f;
    float oacc[8][4];
#pragma unroll
    for (int j = 0; j < 8; j++)
#pragma unroll
        for (int c = 0; c < 4; c++) oacc[j][c] = 0.f;

    load_kv(0, 0);

    for (int kt = 0; kt <= qi; kt++) {
        cp_wait<0>();
        __syncthreads();
        if (kt < qi) load_kv((kt + 1) & 1, kt + 1);

        const uint32_t sK = sb + FKV + (kt & 1) * FSTG, sV = sK + 8192;

        // S = Q @ K^T (64x64x64)
        float sacc[8][4];
#pragma unroll
        for (int j = 0; j < 8; j++)
#pragma unroll
            for (int c = 0; c < 4; c++) sacc[j][c] = 0.f;

#pragma unroll
        for (int ks = 0; ks < 4; ks++) {
            uint32_t aq[4];
            ldsm4(aq, sb + SWZ128((uint32_t)((wq * 16 + (lane & 15)) * 128
                                              + (ks * 2 + (lane >> 4)) * 16)));
#pragma unroll
            for (int bt = 0; bt < 4; bt++) {
                uint32_t bf[4];
                ldsm4(bf, sK + SWZ128((uint32_t)((bt * 16 + ((lane >> 4) << 3) + (lane & 7)) * 128
                                                  + (ks * 2 + ((lane >> 3) & 1)) * 16)));
                mma16816(sacc[2 * bt],     aq, bf);
                mma16816(sacc[2 * bt + 1], aq, bf + 2);
            }
        }

        // scale + causal mask + online softmax
        const int r0 = q0 + wq * 16 + (lane >> 2), r1 = r0 + 8;
        const int cbase = kt * 64 + (lane & 3) * 2;
        const bool diag = (kt == qi);
        float mx0 = -1e30f, mx1 = -1e30f;
#pragma unroll
        for (int j = 0; j < 8; j++) {
#pragma unroll
            for (int c = 0; c < 2; c++) {
                const int col = cbase + j * 8 + c;
                float v0 = sacc[j][c]     * 0.125f;
                float v1 = sacc[j][2 + c] * 0.125f;
                if (diag && col > r0) v0 = -1e30f;
                if (diag && col > r1) v1 = -1e30f;
                sacc[j][c] = v0; sacc[j][2 + c] = v1;
                mx0 = fmaxf(mx0, v0); mx1 = fmaxf(mx1, v1);
            }
        }
        mx0 = fmaxf(mx0, __shfl_xor_sync(0xffffffffu, mx0, 1));
        mx0 = fmaxf(mx0, __shfl_xor_sync(0xffffffffu, mx0, 2));
        mx1 = fmaxf(mx1, __shfl_xor_sync(0xffffffffu, mx1, 1));
        mx1 = fmaxf(mx1, __shfl_xor_sync(0xffffffffu, mx1, 2));

        const float mn0 = fmaxf(m0, mx0), mn1 = fmaxf(m1, mx1);
        const float al0 = __expf(m0 - mn0), al1 = __expf(m1 - mn1);

        uint32_t pf[8][2];
        float rs0 = 0.f, rs1 = 0.f;
#pragma unroll
        for (int j = 0; j < 8; j++) {
            float p0 = __expf(sacc[j][0] - mn0), p1 = __expf(sacc[j][1] - mn0);
            float p2 = __expf(sacc[j][2] - mn1), p3 = __expf(sacc[j][3] - mn1);
            rs0 += p0 + p1; rs1 += p2 + p3;
            __half2 h01 = __floats2half2_rn(p0, p1);
            __half2 h23 = __floats2half2_rn(p2, p3);
            pf[j][0] = *(uint32_t*)&h01;
            pf[j][1] = *(uint32_t*)&h23;
        }
        rs0 += __shfl_xor_sync(0xffffffffu, rs0, 1);
        rs0 += __shfl_xor_sync(0xffffffffu, rs0, 2);
        rs1 += __shfl_xor_sync(0xffffffffu, rs1, 1);
        rs1 += __shfl_xor_sync(0xffffffffu, rs1, 2);

        l0 = l0 * al0 + rs0;  l1 = l1 * al1 + rs1;
        m0 = mn0;             m1 = mn1;
#pragma unroll
        for (int j = 0; j < 8; j++) {
            oacc[j][0] *= al0; oacc[j][1] *= al0;
            oacc[j][2] *= al1; oacc[j][3] *= al1;
        }

        // O += P @ V  (V via ldmatrix.trans)
#pragma unroll
        for (int ks = 0; ks < 4; ks++) {
            uint32_t ap[4] = { pf[2 * ks][0], pf[2 * ks][1], pf[2 * ks + 1][0], pf[2 * ks + 1][1] };
#pragma unroll
            for (int vt = 0; vt < 4; vt++) {
                uint32_t vf[4];
                ldsm4t(vf, sV + SWZ128((uint32_t)((ks * 16 + ((lane >> 3) & 1) * 8 + (lane & 7)) * 128
                                                   + (2 * vt + (lane >> 4)) * 16)));
                mma16816(oacc[2 * vt],     ap, vf);
                mma16816(oacc[2 * vt + 1], ap, vf + 2);
            }
        }
    }

    // epilogue
    const int r0 = q0 + wq * 16 + (lane >> 2), r1 = r0 + 8;
    const float il0 = 1.f / l0, il1 = 1.f / l1;
#pragma unroll
    for (int j = 0; j < 8; j++) {
        const int col = h * 64 + j * 8 + (lane & 3) * 2;
        __half2 v0 = __floats2half2_rn(oacc[j][0] * il0, oacc[j][1] * il0);
        __half2 v1 = __floats2half2_rn(oacc[j][2] * il1, oacc[j][3] * il1);
        *(__half2*)(attnh + (size_t)(b * SEQ + r0) * DIM + col) = v0;
        *(__half2*)(attnh + (size_t)(b * SEQ + r1) * DIM + col) = v1;
    }
}

// ---------------------------------------------------------------------------
extern "C" void kernel_launch(void* const* d_in, const int* in_sizes, int n_in,
                              void* d_out, int out_size)
{
    const float* x    = (const float*)d_in[0];
    const float* Wqkv = (const float*)d_in[1];
    const float* Wout = (const float*)d_in[2];
    float* out = (float*)d_out;

    __half *xh, *wqh, *woh, *qkvh, *atth;
    cudaGetSymbolAddress((void**)&xh,   g_xh);
    cudaGetSymbolAddress((void**)&wqh,  g_wqh);
    cudaGetSymbolAddress((void**)&woh,  g_woh);
    cudaGetSymbolAddress((void**)&qkvh, g_qkvh);
    cudaGetSymbolAddress((void**)&atth, g_atth);

    cudaFuncSetAttribute(gemm_h<true>,  cudaFuncAttributeMaxDynamicSharedMemorySize, GEMM_SMEM);
    cudaFuncSetAttribute(gemm_h<false>, cudaFuncAttributeMaxDynamicSharedMemorySize, GEMM_SMEM);

    // 0) fp32 -> fp16
    to_half<<<(MROWS * DIM)    / 2048, 256>>>(x,    xh,  MROWS * DIM);
    to_half<<<(QKVROW * DIM)   / 2048, 256>>>(Wqkv, wqh, QKVROW * DIM);
    to_half<<<(DIM * DIM)      / 2048, 256>>>(Wout, woh, DIM * DIM);

    // 1) qkv = x @ Wqkv^T  (fp16 out)
    {
        dim3 grid(QKVROW / 128, MROWS / 128);
        gemm_h<true><<<grid, 256, GEMM_SMEM>>>(xh, wqh, qkvh, MROWS, QKVROW, DIM);
    }
    // 2) causal GQA flash attention (fp16 HMMA, fp32 softmax)
    {
        dim3 grid(SEQ / 64, NHEADS, BATCH);
        flash_h<<<grid, 128, FLASH_SMEM>>>(qkvh, atth);
    }
    // 3) out = attn @ Wout^T  (fp32 out)
    {
        dim3 grid(DIM / 128, MROWS / 128);
        gemm_h<false><<<grid, 256, GEMM_SMEM>>>(atth, woh, out, MROWS, DIM, DIM);
    }
}

// round 5
// speedup vs baseline: 8.7314x; 1.0868x over previous
#include <cuda_runtime.h>
#include <cuda_fp16.h>
#include <cstdint>

#define BATCH   2
#define SEQ     2048
#define DIM     2048
#define NHEADS  32
#define NKVH    8
#define HD      64
#define QKVROW  3072
#define MROWS   4096

// ---------------- scratch (__device__ globals; no allocs) ------------------
__device__ __half g_xh  [(size_t)MROWS  * DIM];
__device__ __half g_wqh [(size_t)QKVROW * DIM];
__device__ __half g_woh [(size_t)DIM    * DIM];
__device__ __half g_qkvh[(size_t)MROWS  * QKVROW];
__device__ __half g_atth[(size_t)MROWS  * DIM];

// ---------------- helpers ---------------------------------------------------
__device__ __forceinline__ uint32_t smem_u32(const void* p) {
    uint32_t a;
    asm("{ .reg .u64 t; cvta.to.shared.u64 t, %1; cvt.u32.u64 %0, t; }" : "=r"(a) : "l"(p));
    return a;
}
#define SWZ128(off) ((off) ^ (((off) >> 3) & 0x70))

__device__ __forceinline__ void cp16(uint32_t dst, const void* src) {
    asm volatile("cp.async.cg.shared.global [%0], [%1], 16;" :: "r"(dst), "l"(src) : "memory");
}
__device__ __forceinline__ void cp_commit() {
    asm volatile("cp.async.commit_group;" ::: "memory");
}
template <int N>
__device__ __forceinline__ void cp_wait() {
    asm volatile("cp.async.wait_group %0;" :: "n"(N) : "memory");
}
__device__ __forceinline__ void ldsm4(uint32_t* r, uint32_t addr) {
    asm volatile("ldmatrix.sync.aligned.m8n8.x4.shared.b16 {%0,%1,%2,%3}, [%4];"
                 : "=r"(r[0]), "=r"(r[1]), "=r"(r[2]), "=r"(r[3]) : "r"(addr));
}
__device__ __forceinline__ void ldsm4t(uint32_t* r, uint32_t addr) {
    asm volatile("ldmatrix.sync.aligned.m8n8.x4.trans.shared.b16 {%0,%1,%2,%3}, [%4];"
                 : "=r"(r[0]), "=r"(r[1]), "=r"(r[2]), "=r"(r[3]) : "r"(addr));
}
__device__ __forceinline__ void mma16816(float* c, const uint32_t* a, const uint32_t* b) {
    asm volatile("mma.sync.aligned.m16n8k16.row.col.f32.f16.f16.f32 "
                 "{%0,%1,%2,%3}, {%4,%5,%6,%7}, {%8,%9}, {%0,%1,%2,%3};"
                 : "+f"(c[0]), "+f"(c[1]), "+f"(c[2]), "+f"(c[3])
                 : "r"(a[0]), "r"(a[1]), "r"(a[2]), "r"(a[3]), "r"(b[0]), "r"(b[1]));
}

// ---------------------------------------------------------------------------
// fp32 -> fp16 conversion (memory-bound)
// ---------------------------------------------------------------------------
__global__ void to_half(const float* __restrict__ in, __half* __restrict__ out, int n)
{
    int i = (blockIdx.x * blockDim.x + threadIdx.x) * 8;
    if (i >= n) return;
    float4 a = *(const float4*)(in + i);
    float4 b = *(const float4*)(in + i + 4);
    __half2* o = (__half2*)(out + i);
    o[0] = __floats2half2_rn(a.x, a.y);
    o[1] = __floats2half2_rn(a.z, a.w);
    o[2] = __floats2half2_rn(b.x, b.y);
    o[3] = __floats2half2_rn(b.z, b.w);
}

// ---------------------------------------------------------------------------
// HMMA GEMM: C[M,N] = A[M,K] @ B[N,K]^T   (fp16 in, fp32 accum)
// BM=BN=128, BK=64, 4 warps, warp tile 64x64 (8 LDSM : 32 MMA per k16),
// 3 stages, one sync per iter, loads after barrier. 2 blocks/SM.
// ---------------------------------------------------------------------------
#define GBK   64
#define ASZ   (128 * 128)            // 16384 B per A stage
#define GSTG_B (2 * ASZ)             // 32768 B per stage (A + B)
#define GEMM_SMEM (3 * GSTG_B)       // 98304 B

template<bool HALF_OUT>
__global__ __launch_bounds__(128, 2)
void gemm_h(const __half* __restrict__ A, const __half* __restrict__ B,
            void* __restrict__ Cv, int M, int N, int K)
{
    extern __shared__ char smem[];
    const uint32_t sb0 = smem_u32(smem);
    const int tid = threadIdx.x, lane = tid & 31, wid = tid >> 5;
    const int wm = wid & 1, wn = wid >> 1;
    const int row0 = blockIdx.y * 128, col0 = blockIdx.x * 128;
    const int NITER = K / GBK;

    auto load_stage = [&](int s, int c) {
        const int k0 = c * GBK;
        const uint32_t sA = sb0 + s * GSTG_B, sB = sA + ASZ;
#pragma unroll
        for (int t = 0; t < 8; t++) {
            int idx = tid + t * 128;           // 0..1023 : 128 rows x 8 chunks
            int r = idx >> 3, cc = idx & 7;
            uint32_t off = SWZ128((uint32_t)(r * 128 + cc * 16));
            cp16(sA + off, A + (size_t)(row0 + r) * K + k0 + cc * 8);
            cp16(sB + off, B + (size_t)(col0 + r) * K + k0 + cc * 8);
        }
        cp_commit();
    };

    float acc[4][8][4];
#pragma unroll
    for (int a = 0; a < 4; a++)
#pragma unroll
        for (int b = 0; b < 8; b++)
#pragma unroll
            for (int c = 0; c < 4; c++) acc[a][b][c] = 0.f;

    load_stage(0, 0);
    load_stage(1, 1);

    for (int i = 0; i < NITER; i++) {
        if (i + 1 < NITER) cp_wait<1>(); else cp_wait<0>();
        __syncthreads();
        if (i + 2 < NITER) load_stage((i + 2) % 3, i + 2);

        const uint32_t sA = sb0 + (i % 3) * GSTG_B, sB = sA + ASZ;
#pragma unroll
        for (int ks = 0; ks < 4; ks++) {
            uint32_t af[4][4];
#pragma unroll
            for (int mt = 0; mt < 4; mt++)
                ldsm4(af[mt], sA + SWZ128((uint32_t)((wm * 64 + mt * 16 + (lane & 15)) * 128
                                                      + (ks * 2 + (lane >> 4)) * 16)));
#pragma unroll
            for (int bt = 0; bt < 4; bt++) {
                uint32_t bf[4];
                ldsm4(bf, sB + SWZ128((uint32_t)((wn * 64 + bt * 16 + ((lane >> 4) << 3) + (lane & 7)) * 128
                                                  + (ks * 2 + ((lane >> 3) & 1)) * 16)));
#pragma unroll
                for (int mt = 0; mt < 4; mt++) {
                    mma16816(acc[mt][2 * bt],     af[mt], bf);
                    mma16816(acc[mt][2 * bt + 1], af[mt], bf + 2);
                }
            }
        }
    }

#pragma unroll
    for (int mt = 0; mt < 4; mt++) {
#pragma unroll
        for (int nt = 0; nt < 8; nt++) {
            const int col = col0 + wn * 64 + nt * 8 + (lane & 3) * 2;
            const int r0  = row0 + wm * 64 + mt * 16 + (lane >> 2);
            if (HALF_OUT) {
                __half* C = (__half*)Cv;
                *(__half2*)(C + (size_t)r0 * N + col)       = __floats2half2_rn(acc[mt][nt][0], acc[mt][nt][1]);
                *(__half2*)(C + (size_t)(r0 + 8) * N + col) = __floats2half2_rn(acc[mt][nt][2], acc[mt][nt][3]);
            } else {
                float* C = (float*)Cv;
                *(float2*)(C + (size_t)r0 * N + col)       = make_float2(acc[mt][nt][0], acc[mt][nt][1]);
                *(float2*)(C + (size_t)(r0 + 8) * N + col) = make_float2(acc[mt][nt][2], acc[mt][nt][3]);
            }
        }
    }
}

// ---------------------------------------------------------------------------
// Flash attention, fp16 HMMA. Block = 128 q rows of one head, 4 warps,
// warp tile 32x64. Double-buffered K/V (64-row tiles), one sync per tile.
// smem: Q[16K] + 2 stages of (K[8K] + V[8K]) = 49152 B.
// ---------------------------------------------------------------------------
#define FQ        16384
#define FSTG      16384
#define FLASH_SMEM (FQ + 2 * FSTG)

__global__ __launch_bounds__(128, 2)
void flash_h(const __half* __restrict__ qkv, __half* __restrict__ attnh)
{
    extern __shared__ char smem[];
    const uint32_t sb = smem_u32(smem);
    const int tid = threadIdx.x, lane = tid & 31, wq = tid >> 5;
    const int b = blockIdx.z, h = blockIdx.y;
    const int qi  = gridDim.x - 1 - blockIdx.x;     // heavy tiles first
    const int kvh = h & (NKVH - 1);
    const int q0  = qi * 128;

    // Q tile (128 rows) -> smem
#pragma unroll
    for (int t = 0; t < 8; t++) {
        int idx = tid + t * 128;
        int r = idx >> 3, cc = idx & 7;
        uint4 v = *(const uint4*)(qkv + (size_t)(b * SEQ + q0 + r) * QKVROW + h * HD + cc * 8);
        *(uint4*)(smem + SWZ128((uint32_t)(r * 128 + cc * 16))) = v;
    }

    auto load_kv = [&](int s, int kt) {
        const int k0 = kt * 64;
        const uint32_t sK = sb + FQ + s * FSTG, sV = sK + 8192;
#pragma unroll
        for (int t = 0; t < 4; t++) {
            int idx = tid + t * 128;           // 512 : 64 rows x 8 chunks
            int r = idx >> 3, cc = idx & 7;
            uint32_t off = SWZ128((uint32_t)(r * 128 + cc * 16));
            const __half* base = qkv + (size_t)(b * SEQ + k0 + r) * QKVROW;
            cp16(sK + off, base + (NHEADS + kvh) * HD + cc * 8);
            cp16(sV + off, base + (NHEADS + NKVH + kvh) * HD + cc * 8);
        }
        cp_commit();
    };

    float m_s[4], l_s[4];              // [mt*2 + half]
    float oacc[2][8][4];
#pragma unroll
    for (int i = 0; i < 4; i++) { m_s[i] = -1e30f; l_s[i] = 0.f; }
#pragma unroll
    for (int mt = 0; mt < 2; mt++)
#pragma unroll
        for (int j = 0; j < 8; j++)
#pragma unroll
            for (int c = 0; c < 4; c++) oacc[mt][j][c] = 0.f;

    const int ktmax = 2 * qi + 1;
    load_kv(0, 0);

    for (int kt = 0; kt <= ktmax; kt++) {
        cp_wait<0>();
        __syncthreads();
        if (kt < ktmax) load_kv((kt + 1) & 1, kt + 1);

        const uint32_t sK = sb + FQ + (kt & 1) * FSTG, sV = sK + 8192;

        // S = Q @ K^T  (warp: 32x64, k=64)
        float sacc[2][8][4];
#pragma unroll
        for (int mt = 0; mt < 2; mt++)
#pragma unroll
            for (int j = 0; j < 8; j++)
#pragma unroll
                for (int c = 0; c < 4; c++) sacc[mt][j][c] = 0.f;

#pragma unroll
        for (int ks = 0; ks < 4; ks++) {
            uint32_t aq[2][4];
#pragma unroll
            for (int mt = 0; mt < 2; mt++)
                ldsm4(aq[mt], sb + SWZ128((uint32_t)((wq * 32 + mt * 16 + (lane & 15)) * 128
                                                      + (ks * 2 + (lane >> 4)) * 16)));
#pragma unroll
            for (int bt = 0; bt < 4; bt++) {
                uint32_t bf[4];
                ldsm4(bf, sK + SWZ128((uint32_t)((bt * 16 + ((lane >> 4) << 3) + (lane & 7)) * 128
                                                  + (ks * 2 + ((lane >> 3) & 1)) * 16)));
#pragma unroll
                for (int mt = 0; mt < 2; mt++) {
                    mma16816(sacc[mt][2 * bt],     aq[mt], bf);
                    mma16816(sacc[mt][2 * bt + 1], aq[mt], bf + 2);
                }
            }
        }

        // softmax + P fragments
        uint32_t pf[2][8][2];
#pragma unroll
        for (int mt = 0; mt < 2; mt++) {
            const int r0 = q0 + wq * 32 + mt * 16 + (lane >> 2), r1 = r0 + 8;
            const int cbase = kt * 64 + (lane & 3) * 2;
            const bool diag = (kt * 64 + 63 > r0);   // any masking possible for this row pair
            float mx0 = -1e30f, mx1 = -1e30f;
#pragma unroll
            for (int j = 0; j < 8; j++) {
#pragma unroll
                for (int c = 0; c < 2; c++) {
                    const int col = cbase + j * 8 + c;
                    float v0 = sacc[mt][j][c]     * 0.125f;
                    float v1 = sacc[mt][j][2 + c] * 0.125f;
                    if (diag && col > r0) v0 = -1e30f;
                    if (diag && col > r1) v1 = -1e30f;
                    sacc[mt][j][c] = v0; sacc[mt][j][2 + c] = v1;
                    mx0 = fmaxf(mx0, v0); mx1 = fmaxf(mx1, v1);
                }
            }
            mx0 = fmaxf(mx0, __shfl_xor_sync(0xffffffffu, mx0, 1));
            mx0 = fmaxf(mx0, __shfl_xor_sync(0xffffffffu, mx0, 2));
            mx1 = fmaxf(mx1, __shfl_xor_sync(0xffffffffu, mx1, 1));
            mx1 = fmaxf(mx1, __shfl_xor_sync(0xffffffffu, mx1, 2));

            const float mn0 = fmaxf(m_s[2 * mt], mx0), mn1 = fmaxf(m_s[2 * mt + 1], mx1);
            const float al0 = __expf(m_s[2 * mt] - mn0), al1 = __expf(m_s[2 * mt + 1] - mn1);

            float rs0 = 0.f, rs1 = 0.f;
#pragma unroll
            for (int j = 0; j < 8; j++) {
                float p0 = __expf(sacc[mt][j][0] - mn0), p1 = __expf(sacc[mt][j][1] - mn0);
                float p2 = __expf(sacc[mt][j][2] - mn1), p3 = __expf(sacc[mt][j][3] - mn1);
                rs0 += p0 + p1; rs1 += p2 + p3;
                __half2 h01 = __floats2half2_rn(p0, p1);
                __half2 h23 = __floats2half2_rn(p2, p3);
                pf[mt][j][0] = *(uint32_t*)&h01;
                pf[mt][j][1] = *(uint32_t*)&h23;
            }
            rs0 += __shfl_xor_sync(0xffffffffu, rs0, 1);
            rs0 += __shfl_xor_sync(0xffffffffu, rs0, 2);
            rs1 += __shfl_xor_sync(0xffffffffu, rs1, 1);
            rs1 += __shfl_xor_sync(0xffffffffu, rs1, 2);

            l_s[2 * mt]     = l_s[2 * mt]     * al0 + rs0;
            l_s[2 * mt + 1] = l_s[2 * mt + 1] * al1 + rs1;
            m_s[2 * mt] = mn0; m_s[2 * mt + 1] = mn1;
#pragma unroll
            for (int j = 0; j < 8; j++) {
                oacc[mt][j][0] *= al0; oacc[mt][j][1] *= al0;
                oacc[mt][j][2] *= al1; oacc[mt][j][3] *= al1;
            }
        }

        // O += P @ V  (V via ldmatrix.trans)
#pragma unroll
        for (int ks = 0; ks < 4; ks++) {
#pragma unroll
            for (int vt = 0; vt < 4; vt++) {
                uint32_t vf[4];
                ldsm4t(vf, sV + SWZ128((uint32_t)((ks * 16 + ((lane >> 3) & 1) * 8 + (lane & 7)) * 128
                                                   + (2 * vt + (lane >> 4)) * 16)));
#pragma unroll
                for (int mt = 0; mt < 2; mt++) {
                    uint32_t ap[4] = { pf[mt][2 * ks][0], pf[mt][2 * ks][1],
                                       pf[mt][2 * ks + 1][0], pf[mt][2 * ks + 1][1] };
                    mma16816(oacc[mt][2 * vt],     ap, vf);
                    mma16816(oacc[mt][2 * vt + 1], ap, vf + 2);
                }
            }
        }
    }

    // epilogue
#pragma unroll
    for (int mt = 0; mt < 2; mt++) {
        const int r0 = q0 + wq * 32 + mt * 16 + (lane >> 2), r1 = r0 + 8;
        const float il0 = 1.f / l_s[2 * mt], il1 = 1.f / l_s[2 * mt + 1];
#pragma unroll
        for (int j = 0; j < 8; j++) {
            const int col = h * 64 + j * 8 + (lane & 3) * 2;
            __half2 v0 = __floats2half2_rn(oacc[mt][j][0] * il0, oacc[mt][j][1] * il0);
            __half2 v1 = __floats2half2_rn(oacc[mt][j][2] * il1, oacc[mt][j][3] * il1);
            *(__half2*)(attnh + (size_t)(b * SEQ + r0) * DIM + col) = v0;
            *(__half2*)(attnh + (size_t)(b * SEQ + r1) * DIM + col) = v1;
        }
    }
}

// ---------------------------------------------------------------------------
extern "C" void kernel_launch(void* const* d_in, const int* in_sizes, int n_in,
                              void* d_out, int out_size)
{
    const float* x    = (const float*)d_in[0];
    const float* Wqkv = (const float*)d_in[1];
    const float* Wout = (const float*)d_in[2];
    float* out = (float*)d_out;

    __half *xh, *wqh, *woh, *qkvh, *atth;
    cudaGetSymbolAddress((void**)&xh,   g_xh);
    cudaGetSymbolAddress((void**)&wqh,  g_wqh);
    cudaGetSymbolAddress((void**)&woh,  g_woh);
    cudaGetSymbolAddress((void**)&qkvh, g_qkvh);
    cudaGetSymbolAddress((void**)&atth, g_atth);

    cudaFuncSetAttribute(gemm_h<true>,  cudaFuncAttributeMaxDynamicSharedMemorySize, GEMM_SMEM);
    cudaFuncSetAttribute(gemm_h<false>, cudaFuncAttributeMaxDynamicSharedMemorySize, GEMM_SMEM);
    cudaFuncSetAttribute(flash_h, cudaFuncAttributeMaxDynamicSharedMemorySize, FLASH_SMEM);

    // 0) fp32 -> fp16
    to_half<<<(MROWS * DIM)    / 2048, 256>>>(x,    xh,  MROWS * DIM);
    to_half<<<(QKVROW * DIM)   / 2048, 256>>>(Wqkv, wqh, QKVROW * DIM);
    to_half<<<(DIM * DIM)      / 2048, 256>>>(Wout, woh, DIM * DIM);

    // 1) qkv = x @ Wqkv^T  (fp16 out)
    {
        dim3 grid(QKVROW / 128, MROWS / 128);
        gemm_h<true><<<grid, 128, GEMM_SMEM>>>(xh, wqh, qkvh, MROWS, QKVROW, DIM);
    }
    // 2) causal GQA flash attention (fp16 HMMA, fp32 softmax)
    {
        dim3 grid(SEQ / 128, NHEADS, BATCH);
        flash_h<<<grid, 128, FLASH_SMEM>>>(qkvh, atth);
    }
    // 3) out = attn @ Wout^T  (fp32 out)
    {
        dim3 grid(DIM / 128, MROWS / 128);
        gemm_h<false><<<grid, 128, GEMM_SMEM>>>(atth, woh, out, MROWS, DIM, DIM);
    }
}